// round 2
// baseline (speedup 1.0000x reference)
#include <cuda_runtime.h>

// Problem constants (fixed by the dataset)
#define PB   2      // batch
#define PN   2048   // atoms
#define PM   64     // neighbors
#define PF   128    // features
#define PH1  64
#define PH2  64

// Scratch (allocation-free rule: __device__ globals)
__device__ float g_grad[PB * PN * PF];   // dEi/dx per atom, 4 MB (L2-resident)
__device__ float g_Ei[PB * PN];          // per-atom energies

// ---------------------------------------------------------------------------
// Kernel 1: per-atom sigmoid MLP forward + analytic backward (input gradient)
// Weights live in shared memory. Skewed indexing ((i+j)&63) gives conflict-free
// banks with NO padding, so dynamic smem is exactly 64*128*4 + 64*64*4 = 49152 B.
// ---------------------------------------------------------------------------
__global__ void __launch_bounds__(128) mlp_kernel(
    const float* __restrict__ image,
    const float* __restrict__ W0,     // [H1, F]
    const float* __restrict__ W1,     // [H2, H1]
    const float* __restrict__ Wout)   // [1, H2]
{
    extern __shared__ float dyn[];
    float* sW0 = dyn;                 // 64*128
    float* sW1 = dyn + PH1 * PF;      // 64*64

    __shared__ float sx[PF];
    __shared__ float sh0[PH1];
    __shared__ float sh1[PH2];
    __shared__ float spart[128];
    __shared__ float st0[PH1];
    __shared__ float sWo[PH2];

    const int tid = threadIdx.x;

    for (int i = tid; i < PH1 * PF; i += 128) sW0[i] = W0[i];
    for (int i = tid; i < PH2 * PH1; i += 128) sW1[i] = W1[i];
    if (tid < PH2) sWo[tid] = Wout[tid];
    __syncthreads();

    for (int a = blockIdx.x; a < PB * PN; a += gridDim.x) {
        // stage input row
        sx[tid] = image[(size_t)a * PF + tid];
        __syncthreads();

        // ---- h0 = sigmoid(W0 @ x): 2 threads per output (split F in half) ----
        {
            const int j = tid & 63;          // output index
            const int h = tid >> 6;          // which half of F
            float acc = 0.f;
            #pragma unroll 8
            for (int i = 0; i < 64; i++) {
                const int f = h * 64 + ((i + j) & 63);   // skew: conflict-free
                acc += sW0[j * PF + f] * sx[f];
            }
            spart[tid] = acc;
        }
        __syncthreads();
        if (tid < PH1) {
            const float z = spart[tid] + spart[tid + 64];
            sh0[tid] = 1.f / (1.f + expf(-z));
        }
        __syncthreads();

        // ---- h1 = sigmoid(W1 @ h0), and Ei partials ----
        if (tid < PH2) {
            float z = 0.f;
            #pragma unroll 8
            for (int i = 0; i < 64; i++) {
                const int jj = (i + tid) & 63;           // skew: conflict-free
                z += sW1[tid * PH1 + jj] * sh0[jj];
            }
            const float hv = 1.f / (1.f + expf(-z));
            sh1[tid] = hv;
            spart[tid] = hv * sWo[tid];
        }
        __syncthreads();

        // ---- Ei = sum_k h1[k]*Wout[k] (deterministic warp reduce) ----
        if (tid < 32) {
            float v = spart[tid] + spart[tid + 32];
            #pragma unroll
            for (int o = 16; o; o >>= 1) v += __shfl_down_sync(0xffffffffu, v, o);
            if (tid == 0) g_Ei[a] = v;
        }
        __syncthreads();   // protect spart before reuse below

        // ---- backward: t1 = sigmoid'(h1) * Wout ----
        if (tid < PH2) {
            const float hv = sh1[tid];
            spart[tid] = hv * (1.f - hv) * sWo[tid];
        }
        __syncthreads();

        // ---- gH1[j] = sum_k t1[k]*W1[k,j];  t0 = sigmoid'(h0)*gH1 ----
        if (tid < PH1) {
            float s = 0.f;
            #pragma unroll 8
            for (int k = 0; k < 64; k++) s += spart[k] * sW1[k * PH1 + tid];
            const float h0v = sh0[tid];
            st0[tid] = h0v * (1.f - h0v) * s;
        }
        __syncthreads();

        // ---- g[f] = sum_j t0[j]*W0[j,f] ----
        {
            float s = 0.f;
            #pragma unroll 8
            for (int jj = 0; jj < 64; jj++) s += st0[jj] * sW0[jj * PF + tid];
            g_grad[(size_t)a * PF + tid] = s;
        }
        __syncthreads();   // before overwriting sx on next atom
    }
}

// ---------------------------------------------------------------------------
// Kernel 2: deterministic Etot reduction (no float atomics)
// ---------------------------------------------------------------------------
__global__ void etot_kernel(float* __restrict__ out)
{
    const int b = blockIdx.x;
    const int tid = threadIdx.x;
    __shared__ float sm[256];
    float s = 0.f;
    for (int i = tid; i < PN; i += 256) s += g_Ei[b * PN + i];
    sm[tid] = s;
    __syncthreads();
    #pragma unroll
    for (int o = 128; o; o >>= 1) {
        if (tid < o) sm[tid] += sm[tid + o];
        __syncthreads();
    }
    if (tid == 0) out[b] = sm[0];
}

// ---------------------------------------------------------------------------
// Kernel 3: force[b,n,c] = 1e10 * sum_{m,f} mask * g[b, nei-1, f] * dfeat[b,n,m,f,c]
// One block per (b,n); 128 threads = one per f. dfeat is streamed exactly once,
// fully coalesced (each warp reads 384 contiguous bytes per m-step).
// ---------------------------------------------------------------------------
__global__ void __launch_bounds__(128) force_kernel(
    const float* __restrict__ dfeat,
    const int*   __restrict__ neighbor,
    float*       __restrict__ out)     // out[0..1]=Etot (written by etot), force at out+2
{
    const int bn  = blockIdx.x;        // 0 .. B*N-1
    const int b   = bn >> 11;          // / PN
    const int tid = threadIdx.x;       // f index

    __shared__ int   sidx[PM];
    __shared__ float sred[4][3];

    if (tid < PM) sidx[tid] = neighbor[bn * PM + tid];
    __syncthreads();

    const float* df = dfeat + (size_t)bn * (PM * PF * 3);
    const float* gb = g_grad + (size_t)b * PN * PF;

    float fx = 0.f, fy = 0.f, fz = 0.f;
    for (int m = 0; m < PM; m++) {
        const int nv = sidx[m];
        if (nv > 0) {
            const float gv = gb[(size_t)(nv - 1) * PF + tid];      // coalesced, L2-hit
            const float* dp = df + (size_t)m * (PF * 3) + tid * 3; // coalesced stream
            fx += gv * dp[0];
            fy += gv * dp[1];
            fz += gv * dp[2];
        }
    }

    // reduce 128 threads -> 3 floats
    #pragma unroll
    for (int o = 16; o; o >>= 1) {
        fx += __shfl_down_sync(0xffffffffu, fx, o);
        fy += __shfl_down_sync(0xffffffffu, fy, o);
        fz += __shfl_down_sync(0xffffffffu, fz, o);
    }
    const int w = tid >> 5, l = tid & 31;
    if (l == 0) { sred[w][0] = fx; sred[w][1] = fy; sred[w][2] = fz; }
    __syncthreads();
    if (tid < 3) {
        const float v = sred[0][tid] + sred[1][tid] + sred[2][tid] + sred[3][tid];
        out[2 + bn * 3 + tid] = v * 1e10f;
    }
}

// ---------------------------------------------------------------------------
extern "C" void kernel_launch(void* const* d_in, const int* in_sizes, int n_in,
                              void* d_out, int out_size)
{
    const float* image    = (const float*)d_in[0];
    const float* dfeat    = (const float*)d_in[1];
    const int*   neighbor = (const int*)  d_in[2];
    // d_in[3] Egroup_weight, d_in[4] divider: unused by the reference math
    const float* W0       = (const float*)d_in[5];
    const float* W1       = (const float*)d_in[6];
    const float* Wout     = (const float*)d_in[7];
    float* out = (float*)d_out;

    // 49152 B dynamic smem == default cap; set attribute defensively (not a
    // stream op, capture-safe, no allocation).
    static_assert(PH1 * PF * 4 + PH2 * PH1 * 4 == 49152, "smem layout");
    cudaFuncSetAttribute(mlp_kernel, cudaFuncAttributeMaxDynamicSharedMemorySize, 49152);

    mlp_kernel<<<512, 128, 49152>>>(image, W0, W1, Wout);
    etot_kernel<<<PB, 256>>>(out);
    force_kernel<<<PB * PN, 128>>>(dfeat, neighbor, out);
}

// round 3
// speedup vs baseline: 1.5026x; 1.5026x over previous
#include <cuda_runtime.h>

// Problem constants (fixed by the dataset)
#define PB   2      // batch
#define PN   2048   // atoms
#define PM   64     // neighbors
#define PF   128    // features
#define PH1  64
#define PH2  64

#define NW   4      // warps per MLP block
#define APW  4      // atoms per warp
#define APB  (NW * APW)   // atoms per block = 16

// Scratch (allocation-free rule: __device__ globals)
__device__ float g_grad[PB * PN * PF];   // dEi/dx per atom, 4 MB (L2-resident)
__device__ float g_Ei[PB * PN];          // per-atom energies

// ---------------------------------------------------------------------------
// Kernel 1: warp-private MLP fwd + analytic input-gradient bwd.
// Each warp processes 4 atoms; lane l owns outputs j=l and j=l+32.
// Weights in smem with skew [row][(col+row)&mask] -> conflict-free for both
// row-major (forward) and column-major (backward) reads. No __syncthreads
// in the compute path; only __syncwarp around the per-warp smem buffer.
// ---------------------------------------------------------------------------
__global__ void __launch_bounds__(NW * 32) mlp_kernel(
    const float* __restrict__ image,
    const float* __restrict__ W0,     // [H1, F]
    const float* __restrict__ W1,     // [H2, H1]
    const float* __restrict__ Wout)   // [1, H2]
{
    extern __shared__ float dyn[];
    float* sW0  = dyn;                 // 8192 floats, skewed [j][(f+j)&127]
    float* sW1  = sW0 + PH1 * PF;      // 4096 floats, skewed [k][(j+k)&63]
    float* sX   = sW1 + PH2 * PH1;     // NW*APW*PF = 2048 floats, plain [at][f]
    float* sBuf = sX + NW * APW * PF;  // NW*APW*PH1 = 1024 floats, plain [at][j]
    float* sWo  = sBuf + NW * APW * PH1; // 64 floats

    const int tid = threadIdx.x;
    const int w   = tid >> 5;
    const int l   = tid & 31;

    // ---- stage weights (skewed) ----
    for (int i = tid; i < PH1 * PF; i += NW * 32) {
        const int j = i >> 7, f = i & 127;
        sW0[(j << 7) + ((f + j) & 127)] = W0[i];
    }
    for (int i = tid; i < PH2 * PH1; i += NW * 32) {
        const int k = i >> 6, j = i & 63;
        sW1[(k << 6) + ((j + k) & 63)] = W1[i];
    }
    if (tid < PH2) sWo[tid] = Wout[tid];
    __syncthreads();

    const int a0 = blockIdx.x * APB + w * APW;
    float* wX = sX + w * (APW * PF);
    float* wB = sBuf + w * (APW * PH1);

    // ---- stage x for 4 atoms: 512 contiguous floats, conflict-free ----
    {
        const float4* src = (const float4*)(image + (size_t)a0 * PF);
        float4* dst = (float4*)wX;
        #pragma unroll
        for (int it = 0; it < 4; it++) dst[it * 32 + l] = src[it * 32 + l];
    }
    __syncwarp();

    // ---- L0 forward: h0[j] = sigmoid(sum_f W0[j,f] x[f]), j = l, l+32 ----
    float h0v[2][APW];
    {
        float acc[2][APW];
        #pragma unroll
        for (int h = 0; h < 2; h++)
            #pragma unroll
            for (int at = 0; at < APW; at++) acc[h][at] = 0.f;

        #pragma unroll 2
        for (int f = 0; f < PF; f += 4) {
            float4 xv[APW];
            #pragma unroll
            for (int at = 0; at < APW; at++)
                xv[at] = *(const float4*)(wX + at * PF + f);
            #pragma unroll
            for (int ff = 0; ff < 4; ff++) {
                const float wa = sW0[(l << 7) + ((f + ff + l) & 127)];
                const float wb = sW0[((l + 32) << 7) + ((f + ff + l + 32) & 127)];
                #pragma unroll
                for (int at = 0; at < APW; at++) {
                    const float xe = ((const float*)&xv[at])[ff];
                    acc[0][at] += wa * xe;
                    acc[1][at] += wb * xe;
                }
            }
        }
        #pragma unroll
        for (int h = 0; h < 2; h++)
            #pragma unroll
            for (int at = 0; at < APW; at++)
                h0v[h][at] = 1.f / (1.f + __expf(-acc[h][at]));
    }
    // publish h0 (plain layout, conflict-free: bank = l%32)
    #pragma unroll
    for (int at = 0; at < APW; at++) {
        wB[at * PH1 + l]      = h0v[0][at];
        wB[at * PH1 + l + 32] = h0v[1][at];
    }
    __syncwarp();

    // ---- L1 forward: h1[k] = sigmoid(sum_j W1[k,j] h0[j]), k = l, l+32 ----
    float h1v[2][APW];
    {
        float acc[2][APW];
        #pragma unroll
        for (int h = 0; h < 2; h++)
            #pragma unroll
            for (int at = 0; at < APW; at++) acc[h][at] = 0.f;

        #pragma unroll 2
        for (int j = 0; j < PH1; j += 4) {
            float4 hv[APW];
            #pragma unroll
            for (int at = 0; at < APW; at++)
                hv[at] = *(const float4*)(wB + at * PH1 + j);
            #pragma unroll
            for (int ff = 0; ff < 4; ff++) {
                const float wa = sW1[(l << 6) + ((j + ff + l) & 63)];
                const float wb = sW1[((l + 32) << 6) + ((j + ff + l + 32) & 63)];
                #pragma unroll
                for (int at = 0; at < APW; at++) {
                    const float he = ((const float*)&hv[at])[ff];
                    acc[0][at] += wa * he;
                    acc[1][at] += wb * he;
                }
            }
        }
        #pragma unroll
        for (int h = 0; h < 2; h++)
            #pragma unroll
            for (int at = 0; at < APW; at++)
                h1v[h][at] = 1.f / (1.f + __expf(-acc[h][at]));
    }

    // ---- Ei = sum_k h1[k]*Wout[k] (deterministic warp shuffle reduce) ----
    const float wo0 = sWo[l], wo1 = sWo[l + 32];
    #pragma unroll
    for (int at = 0; at < APW; at++) {
        float v = h1v[0][at] * wo0 + h1v[1][at] * wo1;
        #pragma unroll
        for (int o = 16; o; o >>= 1) v += __shfl_down_sync(0xffffffffu, v, o);
        if (l == 0) g_Ei[a0 + at] = v;
    }
    __syncwarp();   // everyone done reading h0 from wB

    // ---- t1 = h1*(1-h1)*Wout -> publish (overwrites h0 buffer) ----
    #pragma unroll
    for (int at = 0; at < APW; at++) {
        wB[at * PH1 + l]      = h1v[0][at] * (1.f - h1v[0][at]) * wo0;
        wB[at * PH1 + l + 32] = h1v[1][at] * (1.f - h1v[1][at]) * wo1;
    }
    __syncwarp();

    // ---- gH1[j] = sum_k t1[k]*W1[k,j]; t0 = h0*(1-h0)*gH1, j = l, l+32 ----
    float t0v[2][APW];
    {
        float acc[2][APW];
        #pragma unroll
        for (int h = 0; h < 2; h++)
            #pragma unroll
            for (int at = 0; at < APW; at++) acc[h][at] = 0.f;

        #pragma unroll 2
        for (int k = 0; k < PH2; k += 4) {
            float4 tv[APW];
            #pragma unroll
            for (int at = 0; at < APW; at++)
                tv[at] = *(const float4*)(wB + at * PH1 + k);
            #pragma unroll
            for (int kk = 0; kk < 4; kk++) {
                // W1[k][j] at skewed addr (k<<6) + ((j+k)&63)
                const float wa = sW1[((k + kk) << 6) + ((l + k + kk) & 63)];
                const float wb = sW1[((k + kk) << 6) + ((l + 32 + k + kk) & 63)];
                #pragma unroll
                for (int at = 0; at < APW; at++) {
                    const float te = ((const float*)&tv[at])[kk];
                    acc[0][at] += wa * te;
                    acc[1][at] += wb * te;
                }
            }
        }
        #pragma unroll
        for (int h = 0; h < 2; h++)
            #pragma unroll
            for (int at = 0; at < APW; at++)
                t0v[h][at] = h0v[h][at] * (1.f - h0v[h][at]) * acc[h][at];
    }
    __syncwarp();   // done reading t1

    // ---- publish t0 ----
    #pragma unroll
    for (int at = 0; at < APW; at++) {
        wB[at * PH1 + l]      = t0v[0][at];
        wB[at * PH1 + l + 32] = t0v[1][at];
    }
    __syncwarp();

    // ---- g[f] = sum_j t0[j]*W0[j,f], f = l + 32q ----
    {
        float acc[4][APW];
        #pragma unroll
        for (int q = 0; q < 4; q++)
            #pragma unroll
            for (int at = 0; at < APW; at++) acc[q][at] = 0.f;

        for (int j = 0; j < PH1; j += 4) {
            float4 tv[APW];
            #pragma unroll
            for (int at = 0; at < APW; at++)
                tv[at] = *(const float4*)(wB + at * PH1 + j);
            #pragma unroll
            for (int jj = 0; jj < 4; jj++) {
                #pragma unroll
                for (int q = 0; q < 4; q++) {
                    // W0[j][f] at skewed addr (j<<7) + ((f+j)&127)
                    const float wv = sW0[((j + jj) << 7) + ((l + 32 * q + j + jj) & 127)];
                    #pragma unroll
                    for (int at = 0; at < APW; at++)
                        acc[q][at] += wv * ((const float*)&tv[at])[jj];
                }
            }
        }
        #pragma unroll
        for (int at = 0; at < APW; at++)
            #pragma unroll
            for (int q = 0; q < 4; q++)
                g_grad[(size_t)(a0 + at) * PF + l + 32 * q] = acc[q][at];
    }
}

// ---------------------------------------------------------------------------
// Kernel 2: deterministic Etot reduction (no float atomics)
// ---------------------------------------------------------------------------
__global__ void etot_kernel(float* __restrict__ out)
{
    const int b = blockIdx.x;
    const int tid = threadIdx.x;
    __shared__ float sm[256];
    float s = 0.f;
    for (int i = tid; i < PN; i += 256) s += g_Ei[b * PN + i];
    sm[tid] = s;
    __syncthreads();
    #pragma unroll
    for (int o = 128; o; o >>= 1) {
        if (tid < o) sm[tid] += sm[tid + o];
        __syncthreads();
    }
    if (tid == 0) out[b] = sm[0];
}

// ---------------------------------------------------------------------------
// Kernel 3: force[b,n,c] = 1e10 * sum_{m,f} mask * g[b, nei-1, f] * dfeat[b,n,m,f,c]
// Near HBM roofline (streams 402 MB of dfeat once, coalesced). Unchanged.
// ---------------------------------------------------------------------------
__global__ void __launch_bounds__(128) force_kernel(
    const float* __restrict__ dfeat,
    const int*   __restrict__ neighbor,
    float*       __restrict__ out)     // out[0..1]=Etot, force at out+2
{
    const int bn  = blockIdx.x;        // 0 .. B*N-1
    const int b   = bn >> 11;          // / PN
    const int tid = threadIdx.x;       // f index

    __shared__ int   sidx[PM];
    __shared__ float sred[4][3];

    if (tid < PM) sidx[tid] = neighbor[bn * PM + tid];
    __syncthreads();

    const float* df = dfeat + (size_t)bn * (PM * PF * 3);
    const float* gb = g_grad + (size_t)b * PN * PF;

    float fx = 0.f, fy = 0.f, fz = 0.f;
    for (int m = 0; m < PM; m++) {
        const int nv = sidx[m];
        if (nv > 0) {
            const float gv = gb[(size_t)(nv - 1) * PF + tid];      // coalesced, L2-hit
            const float* dp = df + (size_t)m * (PF * 3) + tid * 3; // coalesced stream
            fx += gv * dp[0];
            fy += gv * dp[1];
            fz += gv * dp[2];
        }
    }

    // reduce 128 threads -> 3 floats
    #pragma unroll
    for (int o = 16; o; o >>= 1) {
        fx += __shfl_down_sync(0xffffffffu, fx, o);
        fy += __shfl_down_sync(0xffffffffu, fy, o);
        fz += __shfl_down_sync(0xffffffffu, fz, o);
    }
    const int w = tid >> 5, l = tid & 31;
    if (l == 0) { sred[w][0] = fx; sred[w][1] = fy; sred[w][2] = fz; }
    __syncthreads();
    if (tid < 3) {
        const float v = sred[0][tid] + sred[1][tid] + sred[2][tid] + sred[3][tid];
        out[2 + bn * 3 + tid] = v * 1e10f;
    }
}

// ---------------------------------------------------------------------------
extern "C" void kernel_launch(void* const* d_in, const int* in_sizes, int n_in,
                              void* d_out, int out_size)
{
    const float* image    = (const float*)d_in[0];
    const float* dfeat    = (const float*)d_in[1];
    const int*   neighbor = (const int*)  d_in[2];
    // d_in[3] Egroup_weight, d_in[4] divider: unused by the reference math
    const float* W0       = (const float*)d_in[5];
    const float* W1       = (const float*)d_in[6];
    const float* Wout     = (const float*)d_in[7];
    float* out = (float*)d_out;

    // dynamic smem: W0 8192 + W1 4096 + X 2048 + Buf 1024 + Wo 64 floats
    const int smem_bytes = (PH1 * PF + PH2 * PH1 + NW * APW * PF + NW * APW * PH1 + PH2) * 4;
    cudaFuncSetAttribute(mlp_kernel, cudaFuncAttributeMaxDynamicSharedMemorySize, smem_bytes);

    mlp_kernel<<<(PB * PN) / APB, NW * 32, smem_bytes>>>(image, W0, W1, Wout);
    etot_kernel<<<PB, 256>>>(out);
    force_kernel<<<PB * PN, 128>>>(dfeat, neighbor, out);
}